// round 4
// baseline (speedup 1.0000x reference)
#include <cuda_runtime.h>
#include <math.h>

// ---------------- scratch (no allocations allowed) ----------------
__device__ long long g_rowbase[2048];        // (b*4096+idx)*768 per (b,k)
__device__ float     g_score[2048];          // attention scores, init to v_b
__device__ float     g_z[128 * 768];         // pooled features

#define NEG_INF (-3.402823466e38f)

// ---------------- f32x2 packed-FMA helpers (sm_103a) ----------------
__device__ __forceinline__ void fma2(unsigned long long& acc,
                                     unsigned long long a, unsigned long long b) {
    asm("fma.rn.f32x2 %0, %1, %2, %0;" : "+l"(acc) : "l"(a), "l"(b));
}
__device__ __forceinline__ void unpack2(unsigned long long p, float& x, float& y) {
    asm("mov.b64 {%0, %1}, %2;" : "=f"(x), "=f"(y) : "l"(p));
}

// ---------------- kernel 1: per-batch top-16 of r + fc-bias init ----------------
// 128 blocks x 256 threads. Warp-local top-16 (no block syncs in hot loop),
// then warp 0 merges 8x16 candidates. Also initializes out with fc bias.
__global__ void topk_init_kernel(const float* __restrict__ r,
                                 const float* __restrict__ vb,
                                 float* __restrict__ out,
                                 const float* __restrict__ fcb) {
    const int b = blockIdx.x;
    const int t = threadIdx.x;
    // fc bias init (independent work, overlaps r loads)
    for (int n = t; n < 1000; n += 256) out[b * 1000 + n] = fcb[n];

    const int w = t >> 5, lane = t & 31;
    const float vbv = vb[0];

    float rv[16];
    const float* rp = r + b * 4096 + w * 512 + lane;
#pragma unroll
    for (int j = 0; j < 16; j++) rv[j] = rp[j * 32];

    __shared__ float cv[128];
    __shared__ int   ci[128];

    // phase 1: each warp finds its own top-16 of its 512 elements
    for (int it = 0; it < 16; it++) {
        float bv = rv[0]; int bs = 0;
#pragma unroll
        for (int j = 1; j < 16; j++)
            if (rv[j] > bv) { bv = rv[j]; bs = j; }
        int pay = (lane << 4) | bs;
#pragma unroll
        for (int off = 16; off; off >>= 1) {
            float ov = __shfl_xor_sync(0xffffffffu, bv, off);
            int   op = __shfl_xor_sync(0xffffffffu, pay, off);
            if (ov > bv || (ov == bv && op < pay)) { bv = ov; pay = op; }
        }
        // all lanes agree on (bv, pay)
        if (lane == (pay >> 4)) {
            const int sl = pay & 15;
#pragma unroll
            for (int j = 0; j < 16; j++)
                if (sl == j) rv[j] = NEG_INF;
        }
        if (lane == 0) {
            cv[w * 16 + it] = bv;
            ci[w * 16 + it] = w * 512 + (pay >> 4) + (pay & 15) * 32;
        }
    }
    __syncthreads();

    // phase 2: warp 0 merges 128 candidates -> global top-16
    if (w == 0) {
        float v4[4]; int i4[4];
#pragma unroll
        for (int j = 0; j < 4; j++) { v4[j] = cv[lane * 4 + j]; i4[j] = ci[lane * 4 + j]; }
        for (int it = 0; it < 16; it++) {
            float bv = v4[0]; int bs = 0;
#pragma unroll
            for (int j = 1; j < 4; j++)
                if (v4[j] > bv) { bv = v4[j]; bs = j; }
            int pay = (lane << 2) | bs;
#pragma unroll
            for (int off = 16; off; off >>= 1) {
                float ov = __shfl_xor_sync(0xffffffffu, bv, off);
                int   op = __shfl_xor_sync(0xffffffffu, pay, off);
                if (ov > bv || (ov == bv && op < pay)) { bv = ov; pay = op; }
            }
            const int slot = pay & 3, src = pay >> 2;
            if (lane == src) {
                if (slot == 0) v4[0] = NEG_INF;
                else if (slot == 1) v4[1] = NEG_INF;
                else if (slot == 2) v4[2] = NEG_INF;
                else v4[3] = NEG_INF;
            }
            const int myi = (slot == 0) ? i4[0] : (slot == 1) ? i4[1]
                          : (slot == 2) ? i4[2] : i4[3];
            const int idx = __shfl_sync(0xffffffffu, myi, src);
            if (lane == 0) {
                g_rowbase[b * 16 + it] = ((long long)b * 4096 + idx) * 768;
                g_score[b * 16 + it] = vbv;
            }
        }
    }
}

// ---------------- kernel 2: fused GEMM1 + tanh + v-dot -> score ----------------
// A = gathered x rows [2048,768], B = pool_W_w [768,768].
// 64x64 tile, BK=16, 128 threads. Accumulators are (m-pair, n) packed f32x2 so
// both operands are direct 64-bit smem loads (B stored duplicated). Double
// buffered, one sync per K-step.
__global__ void gemm1_kernel(const float* __restrict__ x,
                             const float* __restrict__ W,
                             const float* __restrict__ Wb,
                             const float* __restrict__ v) {
    __shared__ float As[2][16][64];    // As[buf][k][m]
    __shared__ float Bs[2][16][128];   // Bs[buf][k][2n] duplicated pairs
    __shared__ long long rb[64];

    const int t = threadIdx.x;
    const int n0 = blockIdx.x * 64;
    const int m0 = blockIdx.y * 64;
    if (t < 64) rb[t] = g_rowbase[m0 + t];

    const int tx = t & 15;       // n: 4 per thread
    const int ty = t >> 4;       // m: 8 per thread (4 pairs)
    const int kgA = t >> 6;      // 0..1 ; second load uses kgA+2
    const int mlA = t & 63;
    const int krB = t >> 4;      // 0..7 ; second load uses krB+8
    const int ngB = t & 15;
    __syncthreads();

    const float* aptrA = x + rb[mlA];

    unsigned long long acc[4][4] = {};   // [m_pair][n]
    float4 a0, a1, b0, b1;

#define G1_LOAD(K0)                                                              \
    {                                                                            \
        a0 = *(const float4*)(aptrA + (K0) + kgA * 4);                           \
        a1 = *(const float4*)(aptrA + (K0) + kgA * 4 + 8);                       \
        b0 = *(const float4*)(W + (size_t)((K0) + krB) * 768 + n0 + ngB * 4);    \
        b1 = *(const float4*)(W + (size_t)((K0) + krB + 8) * 768 + n0 + ngB * 4);\
    }
#define G1_STORE(BUF)                                                            \
    {                                                                            \
        As[BUF][kgA * 4 + 0][mlA] = a0.x;                                        \
        As[BUF][kgA * 4 + 1][mlA] = a0.y;                                        \
        As[BUF][kgA * 4 + 2][mlA] = a0.z;                                        \
        As[BUF][kgA * 4 + 3][mlA] = a0.w;                                        \
        As[BUF][kgA * 4 + 8][mlA] = a1.x;                                        \
        As[BUF][kgA * 4 + 9][mlA] = a1.y;                                        \
        As[BUF][kgA * 4 + 10][mlA] = a1.z;                                       \
        As[BUF][kgA * 4 + 11][mlA] = a1.w;                                       \
        *(float4*)&Bs[BUF][krB][ngB * 8]     = make_float4(b0.x, b0.x, b0.y, b0.y); \
        *(float4*)&Bs[BUF][krB][ngB * 8 + 4] = make_float4(b0.z, b0.z, b0.w, b0.w); \
        *(float4*)&Bs[BUF][krB + 8][ngB * 8]     = make_float4(b1.x, b1.x, b1.y, b1.y); \
        *(float4*)&Bs[BUF][krB + 8][ngB * 8 + 4] = make_float4(b1.z, b1.z, b1.w, b1.w); \
    }

    G1_LOAD(0);
    G1_STORE(0);
    __syncthreads();

    int buf = 0;
    for (int k0 = 0; k0 < 768; k0 += 16) {
        const bool more = (k0 + 16) < 768;
        if (more) G1_LOAD(k0 + 16);
#pragma unroll
        for (int k = 0; k < 16; k++) {
            const ulonglong2 a01 = *(const ulonglong2*)&As[buf][k][ty * 8];
            const ulonglong2 a23 = *(const ulonglong2*)&As[buf][k][ty * 8 + 4];
            const ulonglong2 bq0 = *(const ulonglong2*)&Bs[buf][k][tx * 8];
            const ulonglong2 bq1 = *(const ulonglong2*)&Bs[buf][k][tx * 8 + 4];
            unsigned long long ap[4] = {a01.x, a01.y, a23.x, a23.y};
            unsigned long long bp[4] = {bq0.x, bq0.y, bq1.x, bq1.y};
#pragma unroll
            for (int i = 0; i < 4; i++)
#pragma unroll
                for (int j = 0; j < 4; j++) fma2(acc[i][j], ap[i], bp[j]);
        }
        if (more) G1_STORE(buf ^ 1);
        __syncthreads();
        buf ^= 1;
    }

    // epilogue: tanh(h + Wb) dot v -> partial scores, reduce over tx group of 16
    const int nb = n0 + tx * 4;
    const float wb0 = Wb[nb], wb1 = Wb[nb + 1], wb2 = Wb[nb + 2], wb3 = Wb[nb + 3];
    const float vv0 = v[nb], vv1 = v[nb + 1], vv2 = v[nb + 2], vv3 = v[nb + 3];
#pragma unroll
    for (int mp = 0; mp < 4; mp++) {
        float c0e, c0o, c1e, c1o, c2e, c2o, c3e, c3o;
        unpack2(acc[mp][0], c0e, c0o);
        unpack2(acc[mp][1], c1e, c1o);
        unpack2(acc[mp][2], c2e, c2o);
        unpack2(acc[mp][3], c3e, c3o);
        float pe = tanhf(c0e + wb0) * vv0 + tanhf(c1e + wb1) * vv1 +
                   tanhf(c2e + wb2) * vv2 + tanhf(c3e + wb3) * vv3;
        float po = tanhf(c0o + wb0) * vv0 + tanhf(c1o + wb1) * vv1 +
                   tanhf(c2o + wb2) * vv2 + tanhf(c3o + wb3) * vv3;
#pragma unroll
        for (int off = 8; off; off >>= 1) {
            pe += __shfl_xor_sync(0xffffffffu, pe, off, 16);
            po += __shfl_xor_sync(0xffffffffu, po, off, 16);
        }
        if (tx == 0) {
            atomicAdd(&g_score[m0 + ty * 8 + 2 * mp],     pe);
            atomicAdd(&g_score[m0 + ty * 8 + 2 * mp + 1], po);
        }
    }
}

// ---------------- kernel 3: softmax over K=16, z = sum alpha*x ----------------
__global__ void softz_kernel(const float* __restrict__ x) {
    const int b = blockIdx.x;
    const int t = threadIdx.x;  // 192 -> 768/4 float4 per thread
    float sc[16];
#pragma unroll
    for (int k = 0; k < 16; k++) sc[k] = g_score[b * 16 + k];
    float mx = sc[0];
#pragma unroll
    for (int k = 1; k < 16; k++) mx = fmaxf(mx, sc[k]);
    float sum = 0.f;
#pragma unroll
    for (int k = 0; k < 16; k++) { sc[k] = expf(sc[k] - mx); sum += sc[k]; }
    const float inv = 1.0f / sum;

    float4 z = make_float4(0.f, 0.f, 0.f, 0.f);
#pragma unroll
    for (int k = 0; k < 16; k++) {
        const float a = sc[k] * inv;
        const float4 xv = *(const float4*)(x + g_rowbase[b * 16 + k] + t * 4);
        z.x += a * xv.x; z.y += a * xv.y; z.z += a * xv.z; z.w += a * xv.w;
    }
    *(float4*)&g_z[b * 768 + t * 4] = z;
}

// ---------------- kernel 4: fc GEMM [128,768]x[768,1000], split-K, atomic ----------------
__global__ void fc_kernel(const float* __restrict__ Wfc, float* __restrict__ out) {
    __shared__ float As[2][16][64];
    __shared__ float Bs[2][16][128];
    const int t = threadIdx.x;
    const int n0 = blockIdx.x * 64;
    const int m0 = blockIdx.y * 64;
    const int kb = blockIdx.z * 128;
    const int tx = t & 15, ty = t >> 4;
    const int kgA = t >> 6, mlA = t & 63;
    const int krB = t >> 4, ngB = t & 15;

    const float* aptrA = g_z + (m0 + mlA) * 768 + kb;
    const int nB = n0 + ngB * 4;
    const bool nOK = nB < 1000;     // 1000 % 4 == 0: whole float4 in/out

    unsigned long long acc[4][4] = {};
    float4 a0, a1, b0, b1;
    const float4 zero4 = make_float4(0.f, 0.f, 0.f, 0.f);

#define FC_LOAD(K0)                                                               \
    {                                                                             \
        a0 = *(const float4*)(aptrA + (K0) + kgA * 4);                            \
        a1 = *(const float4*)(aptrA + (K0) + kgA * 4 + 8);                        \
        b0 = nOK ? *(const float4*)(Wfc + (size_t)(kb + (K0) + krB) * 1000 + nB) : zero4;      \
        b1 = nOK ? *(const float4*)(Wfc + (size_t)(kb + (K0) + krB + 8) * 1000 + nB) : zero4;  \
    }
#define FC_STORE(BUF)                                                             \
    {                                                                             \
        As[BUF][kgA * 4 + 0][mlA] = a0.x;                                         \
        As[BUF][kgA * 4 + 1][mlA] = a0.y;                                         \
        As[BUF][kgA * 4 + 2][mlA] = a0.z;                                         \
        As[BUF][kgA * 4 + 3][mlA] = a0.w;                                         \
        As[BUF][kgA * 4 + 8][mlA] = a1.x;                                         \
        As[BUF][kgA * 4 + 9][mlA] = a1.y;                                         \
        As[BUF][kgA * 4 + 10][mlA] = a1.z;                                        \
        As[BUF][kgA * 4 + 11][mlA] = a1.w;                                        \
        *(float4*)&Bs[BUF][krB][ngB * 8]     = make_float4(b0.x, b0.x, b0.y, b0.y); \
        *(float4*)&Bs[BUF][krB][ngB * 8 + 4] = make_float4(b0.z, b0.z, b0.w, b0.w); \
        *(float4*)&Bs[BUF][krB + 8][ngB * 8]     = make_float4(b1.x, b1.x, b1.y, b1.y); \
        *(float4*)&Bs[BUF][krB + 8][ngB * 8 + 4] = make_float4(b1.z, b1.z, b1.w, b1.w); \
    }

    FC_LOAD(0);
    FC_STORE(0);
    __syncthreads();

    int buf = 0;
    for (int k0 = 0; k0 < 128; k0 += 16) {
        const bool more = (k0 + 16) < 128;
        if (more) FC_LOAD(k0 + 16);
#pragma unroll
        for (int k = 0; k < 16; k++) {
            const ulonglong2 a01 = *(const ulonglong2*)&As[buf][k][ty * 8];
            const ulonglong2 a23 = *(const ulonglong2*)&As[buf][k][ty * 8 + 4];
            const ulonglong2 bq0 = *(const ulonglong2*)&Bs[buf][k][tx * 8];
            const ulonglong2 bq1 = *(const ulonglong2*)&Bs[buf][k][tx * 8 + 4];
            unsigned long long ap[4] = {a01.x, a01.y, a23.x, a23.y};
            unsigned long long bp[4] = {bq0.x, bq0.y, bq1.x, bq1.y};
#pragma unroll
            for (int i = 0; i < 4; i++)
#pragma unroll
                for (int j = 0; j < 4; j++) fma2(acc[i][j], ap[i], bp[j]);
        }
        if (more) FC_STORE(buf ^ 1);
        __syncthreads();
        buf ^= 1;
    }

#pragma unroll
    for (int mp = 0; mp < 4; mp++) {
        const int me = m0 + ty * 8 + 2 * mp;
#pragma unroll
        for (int j = 0; j < 4; j++) {
            const int n = n0 + tx * 4 + j;
            float ce, co;
            unpack2(acc[mp][j], ce, co);
            if (n < 1000) {
                atomicAdd(&out[me * 1000 + n], ce);
                atomicAdd(&out[(me + 1) * 1000 + n], co);
            }
        }
    }
}

// ---------------- launch ----------------
extern "C" void kernel_launch(void* const* d_in, const int* in_sizes, int n_in,
                              void* d_out, int out_size) {
    const float* x    = (const float*)d_in[0];   // [128,4096,768]
    const float* r    = (const float*)d_in[1];   // [128,4096]
    const float* pWw  = (const float*)d_in[2];   // [768,768]
    const float* pWb  = (const float*)d_in[3];   // [768]
    const float* pVw  = (const float*)d_in[4];   // [768,1]
    const float* pVb  = (const float*)d_in[5];   // [1]
    const float* fcw  = (const float*)d_in[6];   // [768,1000]
    const float* fcb  = (const float*)d_in[7];   // [1000]
    float* out = (float*)d_out;                  // [128,1000]

    topk_init_kernel<<<128, 256>>>(r, pVb, out, fcb);
    gemm1_kernel<<<dim3(12, 32), 128>>>(x, pWw, pWb, pVw);
    softz_kernel<<<128, 192>>>(x);
    fc_kernel<<<dim3(16, 2, 6), 128>>>(fcw, out);
}

// round 6
// speedup vs baseline: 1.0126x; 1.0126x over previous
#include <cuda_runtime.h>
#include <math.h>

// ---------------- scratch (no allocations allowed) ----------------
__device__ long long g_rowbase[2048];        // (b*4096+idx)*768 per (b,k)
__device__ float     g_score[2048];          // attention scores, init to v_b
__device__ float     g_z[128 * 768];         // pooled features

#define NEG_INF (-3.402823466e38f)

// ---------------- f32x2 packed-FMA helpers (sm_103a) ----------------
__device__ __forceinline__ void fma2(unsigned long long& acc,
                                     unsigned long long a, unsigned long long b) {
    asm("fma.rn.f32x2 %0, %1, %2, %0;" : "+l"(acc) : "l"(a), "l"(b));
}
__device__ __forceinline__ unsigned long long dup2(float x) {
    unsigned long long r;
    asm("mov.b64 %0, {%1, %1};" : "=l"(r) : "f"(x));
    return r;
}
__device__ __forceinline__ void unpack2(unsigned long long p, float& x, float& y) {
    asm("mov.b64 {%0, %1}, %2;" : "=f"(x), "=f"(y) : "l"(p));
}

// ---------------- kernel 1: per-batch top-16 of r + fc-bias init ----------------
__global__ void topk_init_kernel(const float* __restrict__ r,
                                 const float* __restrict__ vb,
                                 float* __restrict__ out,
                                 const float* __restrict__ fcb) {
    const int b = blockIdx.x;
    const int t = threadIdx.x;
    for (int n = t; n < 1000; n += 256) out[b * 1000 + n] = fcb[n];

    const int w = t >> 5, lane = t & 31;
    const float vbv = vb[0];

    float rv[16];
    const float* rp = r + b * 4096 + w * 512 + lane;
#pragma unroll
    for (int j = 0; j < 16; j++) rv[j] = rp[j * 32];

    __shared__ float cv[128];
    __shared__ int   ci[128];

    for (int it = 0; it < 16; it++) {
        float bv = rv[0]; int bs = 0;
#pragma unroll
        for (int j = 1; j < 16; j++)
            if (rv[j] > bv) { bv = rv[j]; bs = j; }
        int pay = (lane << 4) | bs;
#pragma unroll
        for (int off = 16; off; off >>= 1) {
            float ov = __shfl_xor_sync(0xffffffffu, bv, off);
            int   op = __shfl_xor_sync(0xffffffffu, pay, off);
            if (ov > bv || (ov == bv && op < pay)) { bv = ov; pay = op; }
        }
        if (lane == (pay >> 4)) {
            const int sl = pay & 15;
#pragma unroll
            for (int j = 0; j < 16; j++)
                if (sl == j) rv[j] = NEG_INF;
        }
        if (lane == 0) {
            cv[w * 16 + it] = bv;
            ci[w * 16 + it] = w * 512 + (pay >> 4) + (pay & 15) * 32;
        }
    }
    __syncthreads();

    if (w == 0) {
        float v4[4]; int i4[4];
#pragma unroll
        for (int j = 0; j < 4; j++) { v4[j] = cv[lane * 4 + j]; i4[j] = ci[lane * 4 + j]; }
        for (int it = 0; it < 16; it++) {
            float bv = v4[0]; int bs = 0;
#pragma unroll
            for (int j = 1; j < 4; j++)
                if (v4[j] > bv) { bv = v4[j]; bs = j; }
            int pay = (lane << 2) | bs;
#pragma unroll
            for (int off = 16; off; off >>= 1) {
                float ov = __shfl_xor_sync(0xffffffffu, bv, off);
                int   op = __shfl_xor_sync(0xffffffffu, pay, off);
                if (ov > bv || (ov == bv && op < pay)) { bv = ov; pay = op; }
            }
            const int slot = pay & 3, src = pay >> 2;
            if (lane == src) {
                if (slot == 0) v4[0] = NEG_INF;
                else if (slot == 1) v4[1] = NEG_INF;
                else if (slot == 2) v4[2] = NEG_INF;
                else v4[3] = NEG_INF;
            }
            const int myi = (slot == 0) ? i4[0] : (slot == 1) ? i4[1]
                          : (slot == 2) ? i4[2] : i4[3];
            const int idx = __shfl_sync(0xffffffffu, myi, src);
            if (lane == 0) {
                g_rowbase[b * 16 + it] = ((long long)b * 4096 + idx) * 768;
                g_score[b * 16 + it] = vbv;
            }
        }
    }
}

// ---------------- kernel 2: fused GEMM1 + tanh + v-dot -> score ----------------
// 64x64 tile, BK=16, 128 threads, double-buffered. A smem = k-major pairs
// (conflict-free 16B reads), B smem = natural rows (16B-stride reads,
// conflict-free); broadcast pairs formed in registers via mov.b64 {x,x}.
__global__ void __launch_bounds__(128) gemm1_kernel(
        const float* __restrict__ x,
        const float* __restrict__ W,
        const float* __restrict__ Wb,
        const float* __restrict__ v) {
    __shared__ float As[2][16][64];    // As[buf][k][m]
    __shared__ float Bs[2][16][68];    // Bs[buf][k][n] (+pad)
    __shared__ long long rb[64];

    const int t = threadIdx.x;
    const int n0 = blockIdx.x * 64;
    const int m0 = blockIdx.y * 64;
    if (t < 64) rb[t] = g_rowbase[m0 + t];

    const int tx = t & 15;       // n: 4 per thread
    const int ty = t >> 4;       // m: 8 per thread (4 pairs)
    const int kgA = t >> 6;      // 0..1
    const int mlA = t & 63;
    const int krB = t >> 4;      // 0..7
    const int ngB = t & 15;
    __syncthreads();

    const float* aptrA = x + rb[mlA];

    unsigned long long acc[4][4] = {};   // [m_pair][n]
    float4 a0, a1, b0, b1;

#define G1_LOAD(K0)                                                              \
    {                                                                            \
        a0 = *(const float4*)(aptrA + (K0) + kgA * 4);                           \
        a1 = *(const float4*)(aptrA + (K0) + kgA * 4 + 8);                       \
        b0 = *(const float4*)(W + (size_t)((K0) + krB) * 768 + n0 + ngB * 4);    \
        b1 = *(const float4*)(W + (size_t)((K0) + krB + 8) * 768 + n0 + ngB * 4);\
    }
#define G1_STORE(BUF)                                                            \
    {                                                                            \
        As[BUF][kgA * 4 + 0][mlA] = a0.x;                                        \
        As[BUF][kgA * 4 + 1][mlA] = a0.y;                                        \
        As[BUF][kgA * 4 + 2][mlA] = a0.z;                                        \
        As[BUF][kgA * 4 + 3][mlA] = a0.w;                                        \
        As[BUF][kgA * 4 + 8][mlA] = a1.x;                                        \
        As[BUF][kgA * 4 + 9][mlA] = a1.y;                                        \
        As[BUF][kgA * 4 + 10][mlA] = a1.z;                                       \
        As[BUF][kgA * 4 + 11][mlA] = a1.w;                                       \
        *(float4*)&Bs[BUF][krB][ngB * 4]     = b0;                               \
        *(float4*)&Bs[BUF][krB + 8][ngB * 4] = b1;                               \
    }
#define G1_INNER(BUF)                                                            \
    _Pragma("unroll")                                                            \
    for (int k = 0; k < 16; k++) {                                               \
        const ulonglong2 a01 = *(const ulonglong2*)&As[BUF][k][ty * 8];          \
        const ulonglong2 a23 = *(const ulonglong2*)&As[BUF][k][ty * 8 + 4];      \
        const float4 bv = *(const float4*)&Bs[BUF][k][tx * 4];                   \
        unsigned long long ap[4] = {a01.x, a01.y, a23.x, a23.y};                 \
        unsigned long long bp[4] = {dup2(bv.x), dup2(bv.y), dup2(bv.z), dup2(bv.w)}; \
        _Pragma("unroll")                                                        \
        for (int i = 0; i < 4; i++)                                              \
            _Pragma("unroll")                                                    \
            for (int j = 0; j < 4; j++) fma2(acc[i][j], ap[i], bp[j]);           \
    }

    G1_LOAD(0);
    G1_STORE(0);
    __syncthreads();

    int buf = 0;
    for (int k0 = 0; k0 < 768; k0 += 16) {
        const bool more = (k0 + 16) < 768;
        if (more) G1_LOAD(k0 + 16);
        G1_INNER(buf);
        if (more) G1_STORE(buf ^ 1);
        __syncthreads();
        buf ^= 1;
    }

    // epilogue: tanh(h + Wb) dot v -> partial scores, reduce over tx group of 16
    const int nb = n0 + tx * 4;
    const float wb0 = Wb[nb], wb1 = Wb[nb + 1], wb2 = Wb[nb + 2], wb3 = Wb[nb + 3];
    const float vv0 = v[nb], vv1 = v[nb + 1], vv2 = v[nb + 2], vv3 = v[nb + 3];
#pragma unroll
    for (int mp = 0; mp < 4; mp++) {
        float c0e, c0o, c1e, c1o, c2e, c2o, c3e, c3o;
        unpack2(acc[mp][0], c0e, c0o);
        unpack2(acc[mp][1], c1e, c1o);
        unpack2(acc[mp][2], c2e, c2o);
        unpack2(acc[mp][3], c3e, c3o);
        float pe = tanhf(c0e + wb0) * vv0 + tanhf(c1e + wb1) * vv1 +
                   tanhf(c2e + wb2) * vv2 + tanhf(c3e + wb3) * vv3;
        float po = tanhf(c0o + wb0) * vv0 + tanhf(c1o + wb1) * vv1 +
                   tanhf(c2o + wb2) * vv2 + tanhf(c3o + wb3) * vv3;
#pragma unroll
        for (int off = 8; off; off >>= 1) {
            pe += __shfl_xor_sync(0xffffffffu, pe, off, 16);
            po += __shfl_xor_sync(0xffffffffu, po, off, 16);
        }
        if (tx == 0) {
            atomicAdd(&g_score[m0 + ty * 8 + 2 * mp],     pe);
            atomicAdd(&g_score[m0 + ty * 8 + 2 * mp + 1], po);
        }
    }
}

// ---------------- kernel 3: softmax over K=16, z = sum alpha*x ----------------
__global__ void softz_kernel(const float* __restrict__ x) {
    const int b = blockIdx.x;
    const int t = threadIdx.x;  // 192 -> 768/4 float4 per thread
    float sc[16];
#pragma unroll
    for (int k = 0; k < 16; k++) sc[k] = g_score[b * 16 + k];
    float mx = sc[0];
#pragma unroll
    for (int k = 1; k < 16; k++) mx = fmaxf(mx, sc[k]);
    float sum = 0.f;
#pragma unroll
    for (int k = 0; k < 16; k++) { sc[k] = expf(sc[k] - mx); sum += sc[k]; }
    const float inv = 1.0f / sum;

    float4 z = make_float4(0.f, 0.f, 0.f, 0.f);
#pragma unroll
    for (int k = 0; k < 16; k++) {
        const float a = sc[k] * inv;
        const float4 xv = *(const float4*)(x + g_rowbase[b * 16 + k] + t * 4);
        z.x += a * xv.x; z.y += a * xv.y; z.z += a * xv.z; z.w += a * xv.w;
    }
    *(float4*)&g_z[b * 768 + t * 4] = z;
}

// ---------------- kernel 4: fc GEMM [128,768]x[768,1000], split-K x12 ----------------
__global__ void __launch_bounds__(128) fc_kernel(
        const float* __restrict__ Wfc, float* __restrict__ out) {
    __shared__ float As[2][16][64];
    __shared__ float Bs[2][16][68];
    const int t = threadIdx.x;
    const int n0 = blockIdx.x * 64;
    const int m0 = blockIdx.y * 64;
    const int kb = blockIdx.z * 64;
    const int tx = t & 15, ty = t >> 4;
    const int kgA = t >> 6, mlA = t & 63;
    const int krB = t >> 4, ngB = t & 15;

    const float* aptrA = g_z + (m0 + mlA) * 768 + kb;
    const int nB = n0 + ngB * 4;
    const bool nOK = nB < 1000;     // 1000 % 4 == 0: whole float4 in/out

    unsigned long long acc[4][4] = {};
    float4 a0, a1, b0, b1;
    const float4 zero4 = make_float4(0.f, 0.f, 0.f, 0.f);

#define FC_LOAD(K0)                                                               \
    {                                                                             \
        a0 = *(const float4*)(aptrA + (K0) + kgA * 4);                            \
        a1 = *(const float4*)(aptrA + (K0) + kgA * 4 + 8);                        \
        b0 = nOK ? *(const float4*)(Wfc + (size_t)(kb + (K0) + krB) * 1000 + nB) : zero4;      \
        b1 = nOK ? *(const float4*)(Wfc + (size_t)(kb + (K0) + krB + 8) * 1000 + nB) : zero4;  \
    }
#define FC_STORE(BUF)                                                             \
    {                                                                             \
        As[BUF][kgA * 4 + 0][mlA] = a0.x;                                         \
        As[BUF][kgA * 4 + 1][mlA] = a0.y;                                         \
        As[BUF][kgA * 4 + 2][mlA] = a0.z;                                         \
        As[BUF][kgA * 4 + 3][mlA] = a0.w;                                         \
        As[BUF][kgA * 4 + 8][mlA] = a1.x;                                         \
        As[BUF][kgA * 4 + 9][mlA] = a1.y;                                         \
        As[BUF][kgA * 4 + 10][mlA] = a1.z;                                        \
        As[BUF][kgA * 4 + 11][mlA] = a1.w;                                        \
        *(float4*)&Bs[BUF][krB][ngB * 4]     = b0;                                \
        *(float4*)&Bs[BUF][krB + 8][ngB * 4] = b1;                                \
    }

    FC_LOAD(0);
    FC_STORE(0);
    __syncthreads();

    int buf = 0;
    for (int k0 = 0; k0 < 64; k0 += 16) {
        const bool more = (k0 + 16) < 64;
        if (more) FC_LOAD(k0 + 16);
#pragma unroll
        for (int k = 0; k < 16; k++) {
            const ulonglong2 a01 = *(const ulonglong2*)&As[buf][k][ty * 8];
            const ulonglong2 a23 = *(const ulonglong2*)&As[buf][k][ty * 8 + 4];
            const float4 bv = *(const float4*)&Bs[buf][k][tx * 4];
            unsigned long long ap[4] = {a01.x, a01.y, a23.x, a23.y};
            unsigned long long bp[4] = {dup2(bv.x), dup2(bv.y), dup2(bv.z), dup2(bv.w)};
#pragma unroll
            for (int i = 0; i < 4; i++)
#pragma unroll
                for (int j = 0; j < 4; j++) fma2(acc[i][j], ap[i], bp[j]);
        }
        if (more) FC_STORE(buf ^ 1);
        __syncthreads();
        buf ^= 1;
    }

#pragma unroll
    for (int mp = 0; mp < 4; mp++) {
        const int me = m0 + ty * 8 + 2 * mp;
#pragma unroll
        for (int j = 0; j < 4; j++) {
            const int n = n0 + tx * 4 + j;
            float ce, co;
            unpack2(acc[mp][j], ce, co);
            if (n < 1000) {
                atomicAdd(&out[me * 1000 + n], ce);
                atomicAdd(&out[(me + 1) * 1000 + n], co);
            }
        }
    }
}

// ---------------- launch ----------------
extern "C" void kernel_launch(void* const* d_in, const int* in_sizes, int n_in,
                              void* d_out, int out_size) {
    const float* x    = (const float*)d_in[0];   // [128,4096,768]
    const float* r    = (const float*)d_in[1];   // [128,4096]
    const float* pWw  = (const float*)d_in[2];   // [768,768]
    const float* pWb  = (const float*)d_in[3];   // [768]
    const float* pVw  = (const float*)d_in[4];   // [768,1]
    const float* pVb  = (const float*)d_in[5];   // [1]
    const float* fcw  = (const float*)d_in[6];   // [768,1000]
    const float* fcb  = (const float*)d_in[7];   // [1000]
    float* out = (float*)d_out;                  // [128,1000]

    topk_init_kernel<<<128, 256>>>(r, pVb, out, fcb);
    gemm1_kernel<<<dim3(12, 32), 128>>>(x, pWw, pWb, pVw);
    softz_kernel<<<128, 192>>>(x);
    fc_kernel<<<dim3(16, 2, 12), 128>>>(fcw, out);
}

// round 8
// speedup vs baseline: 1.9053x; 1.8816x over previous
#include <cuda_runtime.h>
#include <cuda_bf16.h>
#include <math.h>
#include <stdint.h>

// ---------------- scratch (no allocations allowed) ----------------
__device__ long long g_rowbase[2048];              // element offsets into x per (b,k)
__device__ float     g_score[2048];                // attention scores, init v_b
__device__ float     g_z[128 * 768];               // pooled features
__device__ __nv_bfloat16 g_A[2048u * 2304u];       // [Ah | Al | Ah] gathered x rows
__device__ __nv_bfloat16 g_B[768u * 2304u];        // [Bh | Bh | Bl], W^T K-major

#define NEG_INF (-3.402823466e38f)

// ---------------- f32x2 packed-FMA helpers (fc path) ----------------
__device__ __forceinline__ void fma2(unsigned long long& acc,
                                     unsigned long long a, unsigned long long b) {
    asm("fma.rn.f32x2 %0, %1, %2, %0;" : "+l"(acc) : "l"(a), "l"(b));
}
__device__ __forceinline__ unsigned long long dup2(float x) {
    unsigned long long r;
    asm("mov.b64 %0, {%1, %1};" : "=l"(r) : "f"(x));
    return r;
}
__device__ __forceinline__ void unpack2(unsigned long long p, float& x, float& y) {
    asm("mov.b64 {%0, %1}, %2;" : "=f"(x), "=f"(y) : "l"(p));
}

// ---------------- warp-MMA helpers (baseline PTX, works on sm_103) ----------------
__device__ __forceinline__ uint32_t smem_u32(const void* p) {
    uint32_t a;
    asm("{ .reg .u64 t; cvta.to.shared.u64 t, %1; cvt.u32.u64 %0, t; }"
        : "=r"(a) : "l"(p));
    return a;
}
__device__ __forceinline__ void ldsm_x4(uint32_t& r0, uint32_t& r1,
                                        uint32_t& r2, uint32_t& r3, uint32_t addr) {
    asm volatile("ldmatrix.sync.aligned.m8n8.x4.shared.b16 {%0,%1,%2,%3}, [%4];"
                 : "=r"(r0), "=r"(r1), "=r"(r2), "=r"(r3) : "r"(addr));
}
__device__ __forceinline__ void mma16816(float& c0, float& c1, float& c2, float& c3,
                                         uint32_t a0, uint32_t a1, uint32_t a2, uint32_t a3,
                                         uint32_t b0, uint32_t b1) {
    asm volatile("mma.sync.aligned.m16n8k16.row.col.f32.bf16.bf16.f32 "
                 "{%0,%1,%2,%3}, {%4,%5,%6,%7}, {%8,%9}, {%0,%1,%2,%3};"
                 : "+f"(c0), "+f"(c1), "+f"(c2), "+f"(c3)
                 : "r"(a0), "r"(a1), "r"(a2), "r"(a3), "r"(b0), "r"(b1));
}

// ---------------- kernel 1: per-batch top-16 of r + fc-bias init ----------------
__global__ void topk_init_kernel(const float* __restrict__ r,
                                 const float* __restrict__ vb,
                                 float* __restrict__ out,
                                 const float* __restrict__ fcb) {
    const int b = blockIdx.x;
    const int t = threadIdx.x;
    for (int n = t; n < 1000; n += 256) out[b * 1000 + n] = fcb[n];

    const int w = t >> 5, lane = t & 31;
    const float vbv = vb[0];

    float rv[16];
    const float* rp = r + b * 4096 + w * 512 + lane;
#pragma unroll
    for (int j = 0; j < 16; j++) rv[j] = rp[j * 32];

    __shared__ float cv[128];
    __shared__ int   ci[128];

    for (int it = 0; it < 16; it++) {
        float bv = rv[0]; int bs = 0;
#pragma unroll
        for (int j = 1; j < 16; j++)
            if (rv[j] > bv) { bv = rv[j]; bs = j; }
        int pay = (lane << 4) | bs;
#pragma unroll
        for (int off = 16; off; off >>= 1) {
            float ov = __shfl_xor_sync(0xffffffffu, bv, off);
            int   op = __shfl_xor_sync(0xffffffffu, pay, off);
            if (ov > bv || (ov == bv && op < pay)) { bv = ov; pay = op; }
        }
        if (lane == (pay >> 4)) {
            const int sl = pay & 15;
#pragma unroll
            for (int j = 0; j < 16; j++)
                if (sl == j) rv[j] = NEG_INF;
        }
        if (lane == 0) {
            cv[w * 16 + it] = bv;
            ci[w * 16 + it] = w * 512 + (pay >> 4) + (pay & 15) * 32;
        }
    }
    __syncthreads();

    if (w == 0) {
        float v4[4]; int i4[4];
#pragma unroll
        for (int j = 0; j < 4; j++) { v4[j] = cv[lane * 4 + j]; i4[j] = ci[lane * 4 + j]; }
        for (int it = 0; it < 16; it++) {
            float bv = v4[0]; int bs = 0;
#pragma unroll
            for (int j = 1; j < 4; j++)
                if (v4[j] > bv) { bv = v4[j]; bs = j; }
            int pay = (lane << 2) | bs;
#pragma unroll
            for (int off = 16; off; off >>= 1) {
                float ov = __shfl_xor_sync(0xffffffffu, bv, off);
                int   op = __shfl_xor_sync(0xffffffffu, pay, off);
                if (ov > bv || (ov == bv && op < pay)) { bv = ov; pay = op; }
            }
            const int slot = pay & 3, src = pay >> 2;
            if (lane == src) {
                if (slot == 0) v4[0] = NEG_INF;
                else if (slot == 1) v4[1] = NEG_INF;
                else if (slot == 2) v4[2] = NEG_INF;
                else v4[3] = NEG_INF;
            }
            const int myi = (slot == 0) ? i4[0] : (slot == 1) ? i4[1]
                          : (slot == 2) ? i4[2] : i4[3];
            const int idx = __shfl_sync(0xffffffffu, myi, src);
            if (lane == 0) {
                g_rowbase[b * 16 + it] = ((long long)b * 4096 + idx) * 768;
                g_score[b * 16 + it] = vbv;
            }
        }
    }
}

// ---------------- kernel 2a: W -> g_B = [Bh | Bh | Bl], transposed K-major ----------------
__global__ void convW_kernel(const float* __restrict__ W) {
    __shared__ float tile[32][33];
    const int tx = threadIdx.x, ty = threadIdx.y;     // (32, 8)
    const int k0 = blockIdx.x * 32, h0 = blockIdx.y * 32;
#pragma unroll
    for (int i = 0; i < 4; i++)
        tile[ty + i * 8][tx] = W[(size_t)(k0 + ty + i * 8) * 768 + h0 + tx];
    __syncthreads();
#pragma unroll
    for (int i = 0; i < 4; i++) {
        const int h = h0 + ty + i * 8, k = k0 + tx;
        const float val = tile[tx][ty + i * 8];
        const __nv_bfloat16 hi = __float2bfloat16(val);
        const __nv_bfloat16 lo = __float2bfloat16(val - __bfloat162float(hi));
        g_B[(size_t)h * 2304 + k]        = hi;
        g_B[(size_t)h * 2304 + 768 + k]  = hi;
        g_B[(size_t)h * 2304 + 1536 + k] = lo;
    }
}

// ---------------- kernel 2b: gathered x rows -> g_A = [Ah | Al | Ah] ----------------
__global__ void convX_kernel(const float* __restrict__ x) {
    const int b = blockIdx.x;     // 0..2047
    const int t = threadIdx.x;    // 192
    const float4 xv = *(const float4*)(x + g_rowbase[b] + t * 4);
    __nv_bfloat16 h0 = __float2bfloat16(xv.x), h1 = __float2bfloat16(xv.y);
    __nv_bfloat16 h2 = __float2bfloat16(xv.z), h3 = __float2bfloat16(xv.w);
    __nv_bfloat16 l0 = __float2bfloat16(xv.x - __bfloat162float(h0));
    __nv_bfloat16 l1 = __float2bfloat16(xv.y - __bfloat162float(h1));
    __nv_bfloat16 l2 = __float2bfloat16(xv.z - __bfloat162float(h2));
    __nv_bfloat16 l3 = __float2bfloat16(xv.w - __bfloat162float(h3));
    __nv_bfloat162 hh0, hh1, ll0, ll1;
    hh0.x = h0; hh0.y = h1; hh1.x = h2; hh1.y = h3;
    ll0.x = l0; ll0.y = l1; ll1.x = l2; ll1.y = l3;
    __nv_bfloat162* p0 = (__nv_bfloat162*)&g_A[(size_t)b * 2304 + t * 4];
    __nv_bfloat162* p1 = (__nv_bfloat162*)&g_A[(size_t)b * 2304 + 768 + t * 4];
    __nv_bfloat162* p2 = (__nv_bfloat162*)&g_A[(size_t)b * 2304 + 1536 + t * 4];
    p0[0] = hh0; p0[1] = hh1;      // Ah
    p1[0] = ll0; p1[1] = ll1;      // Al (pairs with Bh dup)
    p2[0] = hh0; p2[1] = hh1;      // Ah (pairs with Bl)
}

// ---------------- kernel 3: mma.sync GEMM1 + tanh + v-dot epilogue ----------------
// D[2048 x 768] over K'=2304. Block 256 thr, tile 128x128, BK=32,
// warp grid 4m x 2n, warp tile 32x64 (2x8 m16n8k16). Smem row stride 40 bf16.
static constexpr int G1_NS = 72;   // 2304 / 32

__global__ void __launch_bounds__(256) gemm1_mma(const float* __restrict__ Wb,
                                                 const float* __restrict__ v) {
    __shared__ __nv_bfloat16 As[2][128 * 40];
    __shared__ __nv_bfloat16 Bs[2][128 * 40];
    __shared__ float sWb[128], sv[128];

    const int t = threadIdx.x;
    const int lane = t & 31, w = t >> 5;
    const int wm = w & 3, wn = w >> 2;          // warp tile: rows wm*32, cols wn*64
    const int n0 = blockIdx.x * 128, m0 = blockIdx.y * 128;

    if (t < 128) { sWb[t] = Wb[n0 + t]; sv[t] = v[n0 + t]; }

    // gmem load mapping: 2 passes of 64 rows; row = t/4 (+64), 16B chunk = t%4
    const int lrow = t >> 2, lk8 = (t & 3) * 8;
    const __nv_bfloat16* gA = &g_A[(size_t)(m0 + lrow) * 2304 + lk8];
    const __nv_bfloat16* gB = &g_B[(size_t)(n0 + lrow) * 2304 + lk8];
    uint4 ra0, ra1, rb0, rb1;

#define G1_LDG(S)                                                    \
    {                                                                \
        ra0 = *(const uint4*)(gA + (S) * 32);                        \
        ra1 = *(const uint4*)(gA + (size_t)64 * 2304 + (S) * 32);    \
        rb0 = *(const uint4*)(gB + (S) * 32);                        \
        rb1 = *(const uint4*)(gB + (size_t)64 * 2304 + (S) * 32);    \
    }
#define G1_STS(B)                                                    \
    {                                                                \
        *(uint4*)&As[B][lrow * 40 + lk8]        = ra0;               \
        *(uint4*)&As[B][(lrow + 64) * 40 + lk8] = ra1;               \
        *(uint4*)&Bs[B][lrow * 40 + lk8]        = rb0;               \
        *(uint4*)&Bs[B][(lrow + 64) * 40 + lk8] = rb1;               \
    }

    // ldmatrix lane addressing (byte offsets within a buffer)
    const uint32_t asb = smem_u32(&As[0][0]);
    const uint32_t bsb = smem_u32(&Bs[0][0]);
    const int rowA = wm * 32 + (lane & 15);           // + i*16
    const int colA = (lane >> 4) * 8;                 // + ks*16
    const int nB   = wn * 64 + (lane & 7) + ((lane >> 4) * 8);  // + jp*16
    const int colB = ((lane >> 3) & 1) * 8;           // + ks*16
    const uint32_t aoff = (uint32_t)(rowA * 40 + colA) * 2;
    const uint32_t boff = (uint32_t)(nB * 40 + colB) * 2;

    float acc[2][8][4];
#pragma unroll
    for (int i = 0; i < 2; i++)
#pragma unroll
        for (int j = 0; j < 8; j++)
#pragma unroll
            for (int c = 0; c < 4; c++) acc[i][j][c] = 0.f;

    G1_LDG(0);
    G1_STS(0);
    __syncthreads();

    for (int s = 0; s < G1_NS; s++) {
        const int buf = s & 1;
        if (s + 1 < G1_NS) G1_LDG(s + 1);

        const uint32_t ab = asb + (uint32_t)buf * (128 * 40 * 2);
        const uint32_t bb = bsb + (uint32_t)buf * (128 * 40 * 2);
#pragma unroll
        for (int ks = 0; ks < 2; ks++) {
            uint32_t a[2][4], b[8][2];
#pragma unroll
            for (int i = 0; i < 2; i++)
                ldsm_x4(a[i][0], a[i][1], a[i][2], a[i][3],
                        ab + aoff + (uint32_t)(i * 16 * 40 + ks * 16) * 2);
#pragma unroll
            for (int jp = 0; jp < 4; jp++)
                ldsm_x4(b[jp * 2][0], b[jp * 2][1], b[jp * 2 + 1][0], b[jp * 2 + 1][1],
                        bb + boff + (uint32_t)(jp * 16 * 40 + ks * 16) * 2);
#pragma unroll
            for (int i = 0; i < 2; i++)
#pragma unroll
                for (int j = 0; j < 8; j++)
                    mma16816(acc[i][j][0], acc[i][j][1], acc[i][j][2], acc[i][j][3],
                             a[i][0], a[i][1], a[i][2], a[i][3], b[j][0], b[j][1]);
        }
        if (s + 1 < G1_NS) G1_STS(buf ^ 1);
        __syncthreads();
    }

    // epilogue: frag (i,j,c): row = wm*32+i*16 + lane/4 (+8 for c>=2),
    //                         col = wn*64+j*8 + (lane%4)*2 + (c&1)
    const int cb = wn * 64 + (lane & 3) * 2;
#pragma unroll
    for (int i = 0; i < 2; i++) {
        float sA = 0.f, sB = 0.f;
#pragma unroll
        for (int j = 0; j < 8; j++) {
            const int n = cb + j * 8;
            sA += tanhf(acc[i][j][0] + sWb[n]) * sv[n] +
                  tanhf(acc[i][j][1] + sWb[n + 1]) * sv[n + 1];
            sB += tanhf(acc[i][j][2] + sWb[n]) * sv[n] +
                  tanhf(acc[i][j][3] + sWb[n + 1]) * sv[n + 1];
        }
        sA += __shfl_xor_sync(0xffffffffu, sA, 1);
        sA += __shfl_xor_sync(0xffffffffu, sA, 2);
        sB += __shfl_xor_sync(0xffffffffu, sB, 1);
        sB += __shfl_xor_sync(0xffffffffu, sB, 2);
        if ((lane & 3) == 0) {
            const int m = m0 + wm * 32 + i * 16 + (lane >> 2);
            atomicAdd(&g_score[m], sA);
            atomicAdd(&g_score[m + 8], sB);
        }
    }
}

// ---------------- kernel 4: softmax over K=16, z = sum alpha*x ----------------
__global__ void softz_kernel(const float* __restrict__ x) {
    const int b = blockIdx.x;
    const int t = threadIdx.x;  // 192
    float sc[16];
#pragma unroll
    for (int k = 0; k < 16; k++) sc[k] = g_score[b * 16 + k];
    float mx = sc[0];
#pragma unroll
    for (int k = 1; k < 16; k++) mx = fmaxf(mx, sc[k]);
    float sum = 0.f;
#pragma unroll
    for (int k = 0; k < 16; k++) { sc[k] = expf(sc[k] - mx); sum += sc[k]; }
    const float inv = 1.0f / sum;

    float4 z = make_float4(0.f, 0.f, 0.f, 0.f);
#pragma unroll
    for (int k = 0; k < 16; k++) {
        const float a = sc[k] * inv;
        const float4 xv = *(const float4*)(x + g_rowbase[b * 16 + k] + t * 4);
        z.x += a * xv.x; z.y += a * xv.y; z.z += a * xv.z; z.w += a * xv.w;
    }
    *(float4*)&g_z[b * 768 + t * 4] = z;
}

// ---------------- kernel 5: fc GEMM [128,768]x[768,1000], split-K x24 ----------------
__global__ void __launch_bounds__(128) fc_kernel(
        const float* __restrict__ Wfc, float* __restrict__ out) {
    __shared__ float As[2][16][64];
    __shared__ float Bs[2][16][68];
    const int t = threadIdx.x;
    const int n0 = blockIdx.x * 64;
    const int m0 = blockIdx.y * 64;
    const int kb = blockIdx.z * 32;
    const int tx = t & 15, ty = t >> 4;
    const int kgA = t >> 6, mlA = t & 63;
    const int krB = t >> 4, ngB = t & 15;

    const float* aptrA = g_z + (m0 + mlA) * 768 + kb;
    const int nB = n0 + ngB * 4;
    const bool nOK = nB < 1000;

    unsigned long long acc[4][4] = {};
    float4 a0, a1, b0, b1;
    const float4 zero4 = make_float4(0.f, 0.f, 0.f, 0.f);

#define FC_LOAD(K0)                                                               \
    {                                                                             \
        a0 = *(const float4*)(aptrA + (K0) + kgA * 4);                            \
        a1 = *(const float4*)(aptrA + (K0) + kgA * 4 + 8);                        \
        b0 = nOK ? *(const float4*)(Wfc + (size_t)(kb + (K0) + krB) * 1000 + nB) : zero4;      \
        b1 = nOK ? *(const float4*)(Wfc + (size_t)(kb + (K0) + krB + 8) * 1000 + nB) : zero4;  \
    }
#define FC_STORE(BUF)                                                             \
    {                                                                             \
        As[BUF][kgA * 4 + 0][mlA] = a0.x;                                         \
        As[BUF][kgA * 4 + 1][mlA] = a0.y;                                         \
        As[BUF][kgA * 4 + 2][mlA] = a0.z;                                         \
        As[BUF][kgA * 4 + 3][mlA] = a0.w;                                         \
        As[BUF][kgA * 4 + 8][mlA] = a1.x;                                         \
        As[BUF][kgA * 4 + 9][mlA] = a1.y;                                         \
        As[BUF][kgA * 4 + 10][mlA] = a1.z;                                        \
        As[BUF][kgA * 4 + 11][mlA] = a1.w;                                        \
        *(float4*)&Bs[BUF][krB][ngB * 4]     = b0;                                \
        *(float4*)&Bs[BUF][krB + 8][ngB * 4] = b1;                                \
    }

    FC_LOAD(0);
    FC_STORE(0);
    __syncthreads();

    int buf = 0;
    for (int k0 = 0; k0 < 32; k0 += 16) {
        const bool more = (k0 + 16) < 32;
        if (more) FC_LOAD(k0 + 16);
#pragma unroll
        for (int k = 0; k < 16; k++) {
            const ulonglong2 a01 = *(const ulonglong2*)&As[buf][k][ty * 8];
            const ulonglong2 a23 = *(const ulonglong2*)&As[buf][k][ty * 8 + 4];
            const float4 bv = *(const float4*)&Bs[buf][k][tx * 4];
            unsigned long long ap[4] = {a01.x, a01.y, a23.x, a23.y};
            unsigned long long bp[4] = {dup2(bv.x), dup2(bv.y), dup2(bv.z), dup2(bv.w)};
#pragma unroll
            for (int i = 0; i < 4; i++)
#pragma unroll
                for (int j = 0; j < 4; j++) fma2(acc[i][j], ap[i], bp[j]);
        }
        if (more) FC_STORE(buf ^ 1);
        __syncthreads();
        buf ^= 1;
    }

#pragma unroll
    for (int mp = 0; mp < 4; mp++) {
        const int me = m0 + ty * 8 + 2 * mp;
#pragma unroll
        for (int j = 0; j < 4; j++) {
            const int n = n0 + tx * 4 + j;
            float ce, co;
            unpack2(acc[mp][j], ce, co);
            if (n < 1000) {
                atomicAdd(&out[me * 1000 + n], ce);
                atomicAdd(&out[(me + 1) * 1000 + n], co);
            }
        }
    }
}

// ---------------- launch ----------------
extern "C" void kernel_launch(void* const* d_in, const int* in_sizes, int n_in,
                              void* d_out, int out_size) {
    const float* x    = (const float*)d_in[0];   // [128,4096,768]
    const float* r    = (const float*)d_in[1];   // [128,4096]
    const float* pWw  = (const float*)d_in[2];   // [768,768]
    const float* pWb  = (const float*)d_in[3];   // [768]
    const float* pVw  = (const float*)d_in[4];   // [768,1]
    const float* pVb  = (const float*)d_in[5];   // [1]
    const float* fcw  = (const float*)d_in[6];   // [768,1000]
    const float* fcb  = (const float*)d_in[7];   // [1000]
    float* out = (float*)d_out;                  // [128,1000]

    topk_init_kernel<<<128, 256>>>(r, pVb, out, fcb);
    convW_kernel<<<dim3(24, 24), dim3(32, 8)>>>(pWw);
    convX_kernel<<<2048, 192>>>(x);
    gemm1_mma<<<dim3(6, 16), 256>>>(pWb, pVw);
    softz_kernel<<<128, 192>>>(x);
    fc_kernel<<<dim3(16, 2, 24), 128>>>(fcw, out);
}

// round 9
// speedup vs baseline: 2.3045x; 1.2095x over previous
#include <cuda_runtime.h>
#include <cuda_bf16.h>
#include <math.h>
#include <stdint.h>

// ---------------- scratch (no allocations allowed) ----------------
__device__ long long g_rowbase[2048];               // element offsets into x per (b,k)
__device__ float     g_score[2048];                 // attention scores, init v_b
__device__ __nv_bfloat16 g_A[2048u * 2304u];        // [Ah | Al | Ah] gathered x rows
__device__ __nv_bfloat16 g_B[768u * 2304u];         // [Bh | Bh | Bl], pool_W^T K-major
__device__ __nv_bfloat16 g_zA[128u * 2304u];        // [zh | zl | zh] pooled features
__device__ __nv_bfloat16 g_fcB[1024u * 2304u];      // [Fh | Fh | Fl], fc_w^T K-major (padded)

#define NEG_INF (-3.402823466e38f)

// ---------------- warp-MMA helpers (baseline PTX, works on sm_103) ----------------
__device__ __forceinline__ uint32_t smem_u32(const void* p) {
    uint32_t a;
    asm("{ .reg .u64 t; cvta.to.shared.u64 t, %1; cvt.u32.u64 %0, t; }"
        : "=r"(a) : "l"(p));
    return a;
}
__device__ __forceinline__ void ldsm_x4(uint32_t& r0, uint32_t& r1,
                                        uint32_t& r2, uint32_t& r3, uint32_t addr) {
    asm volatile("ldmatrix.sync.aligned.m8n8.x4.shared.b16 {%0,%1,%2,%3}, [%4];"
                 : "=r"(r0), "=r"(r1), "=r"(r2), "=r"(r3) : "r"(addr));
}
__device__ __forceinline__ void mma16816(float& c0, float& c1, float& c2, float& c3,
                                         uint32_t a0, uint32_t a1, uint32_t a2, uint32_t a3,
                                         uint32_t b0, uint32_t b1) {
    asm volatile("mma.sync.aligned.m16n8k16.row.col.f32.bf16.bf16.f32 "
                 "{%0,%1,%2,%3}, {%4,%5,%6,%7}, {%8,%9}, {%0,%1,%2,%3};"
                 : "+f"(c0), "+f"(c1), "+f"(c2), "+f"(c3)
                 : "r"(a0), "r"(a1), "r"(a2), "r"(a3), "r"(b0), "r"(b1));
}
#define CPA16(dst, src) \
    asm volatile("cp.async.cg.shared.global [%0], [%1], 16;" :: "r"(dst), "l"(src))
#define CPA_COMMIT() asm volatile("cp.async.commit_group;" ::: "memory")
#define CPA_WAIT(N)  asm volatile("cp.async.wait_group %0;" :: "n"(N) : "memory")

__device__ __forceinline__ void f2hilo(float x, __nv_bfloat16& h, __nv_bfloat16& l) {
    h = __float2bfloat16(x);
    l = __float2bfloat16(x - __bfloat162float(h));
}

// ---------------- kernel 1: topk+bias-init | convW | conv fcw ----------------
// blocks [0,128): per-batch top-16 of r + out=fc bias
// blocks [128,704): pool_W -> g_B  (576 = 24 k-tiles x 24 h-tiles)
// blocks [704,1472): fc_w -> g_fcB (768 = 24 k-tiles x 32 n-tiles, pad n>=1000 -> 0)
__global__ void __launch_bounds__(256) prep_kernel(
        const float* __restrict__ r, const float* __restrict__ vb,
        float* __restrict__ out, const float* __restrict__ fcb,
        const float* __restrict__ W, const float* __restrict__ fcw) {
    const int bid = blockIdx.x;
    const int t = threadIdx.x;

    if (bid >= 128) {
        __shared__ float tile[32][33];
        const int tx = t & 31, rt = t >> 5;    // 32 x 8
        if (bid < 704) {
            const int b2 = bid - 128;
            const int k0 = (b2 % 24) * 32, h0 = (b2 / 24) * 32;
#pragma unroll
            for (int i = 0; i < 4; i++)
                tile[rt + i * 8][tx] = W[(size_t)(k0 + rt + i * 8) * 768 + h0 + tx];
            __syncthreads();
#pragma unroll
            for (int i = 0; i < 4; i++) {
                const int h = h0 + rt + i * 8, k = k0 + tx;
                __nv_bfloat16 hi, lo;
                f2hilo(tile[tx][rt + i * 8], hi, lo);
                g_B[(size_t)h * 2304 + k]        = hi;
                g_B[(size_t)h * 2304 + 768 + k]  = hi;
                g_B[(size_t)h * 2304 + 1536 + k] = lo;
            }
        } else {
            const int b3 = bid - 704;
            const int k0 = (b3 % 24) * 32, n0 = (b3 / 24) * 32;
#pragma unroll
            for (int i = 0; i < 4; i++)
                tile[rt + i * 8][tx] = (n0 + tx < 1000)
                    ? fcw[(size_t)(k0 + rt + i * 8) * 1000 + n0 + tx] : 0.f;
            __syncthreads();
#pragma unroll
            for (int i = 0; i < 4; i++) {
                const int n = n0 + rt + i * 8, k = k0 + tx;
                __nv_bfloat16 hi, lo;
                f2hilo(tile[tx][rt + i * 8], hi, lo);
                g_fcB[(size_t)n * 2304 + k]        = hi;
                g_fcB[(size_t)n * 2304 + 768 + k]  = hi;
                g_fcB[(size_t)n * 2304 + 1536 + k] = lo;
            }
        }
        return;
    }

    // ---- topk + bias init ----
    const int b = bid;
    for (int n = t; n < 1000; n += 256) out[b * 1000 + n] = fcb[n];

    const int w = t >> 5, lane = t & 31;
    const float vbv = vb[0];
    float rv[16];
    const float* rp = r + b * 4096 + w * 512 + lane;
#pragma unroll
    for (int j = 0; j < 16; j++) rv[j] = rp[j * 32];

    __shared__ float cv[128];
    __shared__ int   ci[128];

    for (int it = 0; it < 16; it++) {
        float bv = rv[0]; int bs = 0;
#pragma unroll
        for (int j = 1; j < 16; j++)
            if (rv[j] > bv) { bv = rv[j]; bs = j; }
        int pay = (lane << 4) | bs;
#pragma unroll
        for (int off = 16; off; off >>= 1) {
            float ov = __shfl_xor_sync(0xffffffffu, bv, off);
            int   op = __shfl_xor_sync(0xffffffffu, pay, off);
            if (ov > bv || (ov == bv && op < pay)) { bv = ov; pay = op; }
        }
        if (lane == (pay >> 4)) {
            const int sl = pay & 15;
#pragma unroll
            for (int j = 0; j < 16; j++)
                if (sl == j) rv[j] = NEG_INF;
        }
        if (lane == 0) {
            cv[w * 16 + it] = bv;
            ci[w * 16 + it] = w * 512 + (pay >> 4) + (pay & 15) * 32;
        }
    }
    __syncthreads();

    if (w == 0) {
        float v4[4]; int i4[4];
#pragma unroll
        for (int j = 0; j < 4; j++) { v4[j] = cv[lane * 4 + j]; i4[j] = ci[lane * 4 + j]; }
        for (int it = 0; it < 16; it++) {
            float bv = v4[0]; int bs = 0;
#pragma unroll
            for (int j = 1; j < 4; j++)
                if (v4[j] > bv) { bv = v4[j]; bs = j; }
            int pay = (lane << 2) | bs;
#pragma unroll
            for (int off = 16; off; off >>= 1) {
                float ov = __shfl_xor_sync(0xffffffffu, bv, off);
                int   op = __shfl_xor_sync(0xffffffffu, pay, off);
                if (ov > bv || (ov == bv && op < pay)) { bv = ov; pay = op; }
            }
            const int slot = pay & 3, src = pay >> 2;
            if (lane == src) {
                if (slot == 0) v4[0] = NEG_INF;
                else if (slot == 1) v4[1] = NEG_INF;
                else if (slot == 2) v4[2] = NEG_INF;
                else v4[3] = NEG_INF;
            }
            const int myi = (slot == 0) ? i4[0] : (slot == 1) ? i4[1]
                          : (slot == 2) ? i4[2] : i4[3];
            const int idx = __shfl_sync(0xffffffffu, myi, src);
            if (lane == 0) {
                g_rowbase[b * 16 + it] = ((long long)b * 4096 + idx) * 768;
                g_score[b * 16 + it] = vbv;
            }
        }
    }
}

// ---------------- kernel 2: gathered x rows -> g_A = [Ah | Al | Ah] ----------------
__global__ void convX_kernel(const float* __restrict__ x) {
    const int b = blockIdx.x;     // 0..2047
    const int t = threadIdx.x;    // 192
    const float4 xv = *(const float4*)(x + g_rowbase[b] + t * 4);
    __nv_bfloat16 h0, h1, h2, h3, l0, l1, l2, l3;
    f2hilo(xv.x, h0, l0); f2hilo(xv.y, h1, l1);
    f2hilo(xv.z, h2, l2); f2hilo(xv.w, h3, l3);
    __nv_bfloat162 hh0, hh1, ll0, ll1;
    hh0.x = h0; hh0.y = h1; hh1.x = h2; hh1.y = h3;
    ll0.x = l0; ll0.y = l1; ll1.x = l2; ll1.y = l3;
    __nv_bfloat162* p0 = (__nv_bfloat162*)&g_A[(size_t)b * 2304 + t * 4];
    __nv_bfloat162* p1 = (__nv_bfloat162*)&g_A[(size_t)b * 2304 + 768 + t * 4];
    __nv_bfloat162* p2 = (__nv_bfloat162*)&g_A[(size_t)b * 2304 + 1536 + t * 4];
    p0[0] = hh0; p0[1] = hh1;
    p1[0] = ll0; p1[1] = ll1;
    p2[0] = hh0; p2[1] = hh1;
}

// ---------------- kernel 3: mma GEMM1 + tanh + v-dot epilogue ----------------
// Tile 64x64, BK=32, 128 thr / 4 warps (2m x 2n, warp tile 32x32),
// 3-stage cp.async pipeline. grid (12, 32) = 384 blocks.
static constexpr int G1_NS = 72;   // 2304/32

__global__ void __launch_bounds__(128) gemm1_mma(const float* __restrict__ Wb,
                                                 const float* __restrict__ v) {
    __shared__ __nv_bfloat16 As[3][64 * 40];
    __shared__ __nv_bfloat16 Bs[3][64 * 40];
    __shared__ float sWb[64], sv[64];

    const int t = threadIdx.x, lane = t & 31, w = t >> 5;
    const int wm = w & 1, wn = w >> 1;
    const int n0 = blockIdx.x * 64, m0 = blockIdx.y * 64;
    if (t < 64) { sWb[t] = Wb[n0 + t]; sv[t] = v[n0 + t]; }

    const int r0 = t >> 2, kc0 = (t & 3) * 8;     // rows r0, r0+32
    const uint32_t sA = smem_u32(As), sB = smem_u32(Bs);
    const uint32_t dOff = (uint32_t)(r0 * 40 + kc0) * 2u;

#define G1_ISSUE(S, BUF)                                                        \
    {                                                                           \
        const uint32_t dA = sA + (BUF) * 5120u + dOff;                          \
        const uint32_t dB = sB + (BUF) * 5120u + dOff;                          \
        CPA16(dA,         &g_A[(size_t)(m0 + r0) * 2304 + (S) * 32 + kc0]);     \
        CPA16(dA + 2560u, &g_A[(size_t)(m0 + r0 + 32) * 2304 + (S) * 32 + kc0]);\
        CPA16(dB,         &g_B[(size_t)(n0 + r0) * 2304 + (S) * 32 + kc0]);     \
        CPA16(dB + 2560u, &g_B[(size_t)(n0 + r0 + 32) * 2304 + (S) * 32 + kc0]);\
    }

    const uint32_t aoff = (uint32_t)((wm * 32 + (lane & 15)) * 40 + (lane >> 4) * 8) * 2u;
    const uint32_t boff = (uint32_t)((wn * 32 + (lane & 7) + (lane >> 4) * 8) * 40 +
                                     ((lane >> 3) & 1) * 8) * 2u;

    float acc[2][4][4];
#pragma unroll
    for (int i = 0; i < 2; i++)
#pragma unroll
        for (int j = 0; j < 4; j++)
#pragma unroll
            for (int c = 0; c < 4; c++) acc[i][j][c] = 0.f;

    G1_ISSUE(0, 0); CPA_COMMIT();
    G1_ISSUE(1, 1); CPA_COMMIT();

    for (int s = 0; s < G1_NS; s++) {
        const int buf = s % 3;
        CPA_WAIT(1);
        __syncthreads();
        if (s + 2 < G1_NS) { const int nb = (s + 2) % 3; G1_ISSUE(s + 2, nb); }
        CPA_COMMIT();

        const uint32_t ab = sA + (uint32_t)buf * 5120u;
        const uint32_t bb = sB + (uint32_t)buf * 5120u;
#pragma unroll
        for (int ks = 0; ks < 2; ks++) {
            uint32_t a[2][4], b2[4][2];
#pragma unroll
            for (int i = 0; i < 2; i++)
                ldsm_x4(a[i][0], a[i][1], a[i][2], a[i][3],
                        ab + aoff + (uint32_t)(i * 16 * 40 + ks * 16) * 2u);
#pragma unroll
            for (int jp = 0; jp < 2; jp++)
                ldsm_x4(b2[jp * 2][0], b2[jp * 2][1], b2[jp * 2 + 1][0], b2[jp * 2 + 1][1],
                        bb + boff + (uint32_t)(jp * 16 * 40 + ks * 16) * 2u);
#pragma unroll
            for (int i = 0; i < 2; i++)
#pragma unroll
                for (int j = 0; j < 4; j++)
                    mma16816(acc[i][j][0], acc[i][j][1], acc[i][j][2], acc[i][j][3],
                             a[i][0], a[i][1], a[i][2], a[i][3], b2[j][0], b2[j][1]);
        }
        __syncthreads();
    }

    // epilogue: row = wm*32+i*16+lane/4 (+8 for c>=2), col = wn*32+(lane&3)*2+j*8+(c&1)
    const int cb = wn * 32 + (lane & 3) * 2;
#pragma unroll
    for (int i = 0; i < 2; i++) {
        float pA = 0.f, pB = 0.f;
#pragma unroll
        for (int j = 0; j < 4; j++) {
            const int n = cb + j * 8;
            pA += tanhf(acc[i][j][0] + sWb[n]) * sv[n] +
                  tanhf(acc[i][j][1] + sWb[n + 1]) * sv[n + 1];
            pB += tanhf(acc[i][j][2] + sWb[n]) * sv[n] +
                  tanhf(acc[i][j][3] + sWb[n + 1]) * sv[n + 1];
        }
        pA += __shfl_xor_sync(0xffffffffu, pA, 1);
        pA += __shfl_xor_sync(0xffffffffu, pA, 2);
        pB += __shfl_xor_sync(0xffffffffu, pB, 1);
        pB += __shfl_xor_sync(0xffffffffu, pB, 2);
        if ((lane & 3) == 0) {
            const int m = m0 + wm * 32 + i * 16 + (lane >> 2);
            atomicAdd(&g_score[m], pA);
            atomicAdd(&g_score[m + 8], pB);
        }
    }
}

// ---------------- kernel 4: softmax + z, emit z as [zh | zl | zh] ----------------
__global__ void softz_kernel(const float* __restrict__ x) {
    const int b = blockIdx.x;
    const int t = threadIdx.x;  // 192
    float sc[16];
#pragma unroll
    for (int k = 0; k < 16; k++) sc[k] = g_score[b * 16 + k];
    float mx = sc[0];
#pragma unroll
    for (int k = 1; k < 16; k++) mx = fmaxf(mx, sc[k]);
    float sum = 0.f;
#pragma unroll
    for (int k = 0; k < 16; k++) { sc[k] = expf(sc[k] - mx); sum += sc[k]; }
    const float inv = 1.0f / sum;

    float4 z = make_float4(0.f, 0.f, 0.f, 0.f);
#pragma unroll
    for (int k = 0; k < 16; k++) {
        const float a = sc[k] * inv;
        const float4 xv = *(const float4*)(x + g_rowbase[b * 16 + k] + t * 4);
        z.x += a * xv.x; z.y += a * xv.y; z.z += a * xv.z; z.w += a * xv.w;
    }
    __nv_bfloat16 h0, h1, h2, h3, l0, l1, l2, l3;
    f2hilo(z.x, h0, l0); f2hilo(z.y, h1, l1);
    f2hilo(z.z, h2, l2); f2hilo(z.w, h3, l3);
    __nv_bfloat162 hh0, hh1, ll0, ll1;
    hh0.x = h0; hh0.y = h1; hh1.x = h2; hh1.y = h3;
    ll0.x = l0; ll0.y = l1; ll1.x = l2; ll1.y = l3;
    __nv_bfloat162* p0 = (__nv_bfloat162*)&g_zA[(size_t)b * 2304 + t * 4];
    __nv_bfloat162* p1 = (__nv_bfloat162*)&g_zA[(size_t)b * 2304 + 768 + t * 4];
    __nv_bfloat162* p2 = (__nv_bfloat162*)&g_zA[(size_t)b * 2304 + 1536 + t * 4];
    p0[0] = hh0; p0[1] = hh1;
    p1[0] = ll0; p1[1] = ll1;
    p2[0] = hh0; p2[1] = hh1;
}

// ---------------- kernel 5: fc via mma, split-K'x6, atomicAdd ----------------
// Tile 64x64, BK=32, 128 thr, grid (16, 2, 6); out pre-initialized with bias.
static constexpr int FC_NS = 12;   // 384/32

__global__ void __launch_bounds__(128) fc_mma(float* __restrict__ out) {
    __shared__ __nv_bfloat16 As[3][64 * 40];
    __shared__ __nv_bfloat16 Bs[3][64 * 40];

    const int t = threadIdx.x, lane = t & 31, w = t >> 5;
    const int wm = w & 1, wn = w >> 1;
    const int n0 = blockIdx.x * 64, m0 = blockIdx.y * 64;
    const int kb = blockIdx.z * 384;

    const int r0 = t >> 2, kc0 = (t & 3) * 8;
    const uint32_t sA = smem_u32(As), sB = smem_u32(Bs);
    const uint32_t dOff = (uint32_t)(r0 * 40 + kc0) * 2u;

#define FC_ISSUE(S, BUF)                                                             \
    {                                                                                \
        const uint32_t dA = sA + (BUF) * 5120u + dOff;                               \
        const uint32_t dB = sB + (BUF) * 5120u + dOff;                               \
        CPA16(dA,         &g_zA[(size_t)(m0 + r0) * 2304 + kb + (S) * 32 + kc0]);    \
        CPA16(dA + 2560u, &g_zA[(size_t)(m0 + r0 + 32) * 2304 + kb + (S) * 32 + kc0]);\
        CPA16(dB,         &g_fcB[(size_t)(n0 + r0) * 2304 + kb + (S) * 32 + kc0]);   \
        CPA16(dB + 2560u, &g_fcB[(size_t)(n0 + r0 + 32) * 2304 + kb + (S) * 32 + kc0]);\
    }

    const uint32_t aoff = (uint32_t)((wm * 32 + (lane & 15)) * 40 + (lane >> 4) * 8) * 2u;
    const uint32_t boff = (uint32_t)((wn * 32 + (lane & 7) + (lane >> 4) * 8) * 40 +
                                     ((lane >> 3) & 1) * 8) * 2u;

    float acc[2][4][4];
#pragma unroll
    for (int i = 0; i < 2; i++)
#pragma unroll
        for (int j = 0; j < 4; j++)
#pragma unroll
            for (int c = 0; c < 4; c++) acc[i][j][c] = 0.f;

    FC_ISSUE(0, 0); CPA_COMMIT();
    FC_ISSUE(1, 1); CPA_COMMIT();

    for (int s = 0; s < FC_NS; s++) {
        const int buf = s % 3;
        CPA_WAIT(1);
        __syncthreads();
        if (s + 2 < FC_NS) { const int nb = (s + 2) % 3; FC_ISSUE(s + 2, nb); }
        CPA_COMMIT();

        const uint32_t ab = sA + (uint32_t)buf * 5120u;
        const uint32_t bb = sB + (uint32_t)buf * 5120u;
#pragma unroll
        for (int ks = 0; ks < 2; ks++) {
            uint32_t a[2][4], b2[4][2];
#pragma unroll
            for (int i = 0; i < 2; i++)
                ldsm_x4(a[i][0], a[i][1], a[i][2], a[i][3],
                        ab + aoff + (uint32_t)(i * 16 * 40 + ks * 16) * 2u);
#pragma unroll
            for (int jp = 0; jp < 2; jp++)
                ldsm_x4(b2[jp * 2][0], b2[jp * 2][1], b2[jp * 2 + 1][0], b2[jp * 2 + 1][1],
                        bb + boff + (uint32_t)(jp * 16 * 40 + ks * 16) * 2u);
#pragma unroll
            for (int i = 0; i < 2; i++)
#pragma unroll
                for (int j = 0; j < 4; j++)
                    mma16816(acc[i][j][0], acc[i][j][1], acc[i][j][2], acc[i][j][3],
                             a[i][0], a[i][1], a[i][2], a[i][3], b2[j][0], b2[j][1]);
        }
        __syncthreads();
    }

#pragma unroll
    for (int i = 0; i < 2; i++) {
        const int m = m0 + wm * 32 + i * 16 + (lane >> 2);
#pragma unroll
        for (int j = 0; j < 4; j++) {
            const int n = n0 + wn * 32 + (lane & 3) * 2 + j * 8;
            if (n < 1000) {
                atomicAdd(&out[m * 1000 + n], acc[i][j][0]);
                atomicAdd(&out[(m + 8) * 1000 + n], acc[i][j][2]);
            }
            if (n + 1 < 1000) {
                atomicAdd(&out[m * 1000 + n + 1], acc[i][j][1]);
                atomicAdd(&out[(m + 8) * 1000 + n + 1], acc[i][j][3]);
            }
        }
    }
}

// ---------------- launch ----------------
extern "C" void kernel_launch(void* const* d_in, const int* in_sizes, int n_in,
                              void* d_out, int out_size) {
    const float* x    = (const float*)d_in[0];   // [128,4096,768]
    const float* r    = (const float*)d_in[1];   // [128,4096]
    const float* pWw  = (const float*)d_in[2];   // [768,768]
    const float* pWb  = (const float*)d_in[3];   // [768]
    const float* pVw  = (const float*)d_in[4];   // [768,1]
    const float* pVb  = (const float*)d_in[5];   // [1]
    const float* fcw  = (const float*)d_in[6];   // [768,1000]
    const float* fcb  = (const float*)d_in[7];   // [1000]
    float* out = (float*)d_out;                  // [128,1000]

    prep_kernel<<<1472, 256>>>(r, pVb, out, fcb, pWw, fcw);
    convX_kernel<<<2048, 192>>>(x);
    gemm1_mma<<<dim3(12, 32), 128>>>(pWb, pVw);
    softz_kernel<<<128, 192>>>(x);
    fc_mma<<<dim3(16, 2, 6), 128>>>(out);
}

// round 10
// speedup vs baseline: 2.3066x; 1.0009x over previous
#include <cuda_runtime.h>
#include <cuda_bf16.h>
#include <math.h>
#include <stdint.h>

// ---------------- scratch (no allocations allowed) ----------------
__device__ long long g_rowbase[2048];               // element offsets into x per (b,k)
__device__ float     g_score[2048];                 // attention scores, init v_b
__device__ __nv_bfloat16 g_A[2048u * 2304u];        // [Ah | Al | Ah] gathered x rows
__device__ __nv_bfloat16 g_B[768u * 2304u];         // [Bh | Bh | Bl], pool_W^T K-major
__device__ __nv_bfloat16 g_zA[128u * 2304u];        // [zh | zl | zh] pooled features
__device__ __nv_bfloat16 g_fcB[1024u * 2304u];      // [Fh | Fh | Fl], fc_w^T K-major (padded)

#define NEG_INF (-3.402823466e38f)

// ---------------- warp-MMA helpers (baseline PTX, works on sm_103) ----------------
__device__ __forceinline__ uint32_t smem_u32(const void* p) {
    uint32_t a;
    asm("{ .reg .u64 t; cvta.to.shared.u64 t, %1; cvt.u32.u64 %0, t; }"
        : "=r"(a) : "l"(p));
    return a;
}
__device__ __forceinline__ void ldsm_x4(uint32_t& r0, uint32_t& r1,
                                        uint32_t& r2, uint32_t& r3, uint32_t addr) {
    asm volatile("ldmatrix.sync.aligned.m8n8.x4.shared.b16 {%0,%1,%2,%3}, [%4];"
                 : "=r"(r0), "=r"(r1), "=r"(r2), "=r"(r3) : "r"(addr));
}
__device__ __forceinline__ void mma16816(float& c0, float& c1, float& c2, float& c3,
                                         uint32_t a0, uint32_t a1, uint32_t a2, uint32_t a3,
                                         uint32_t b0, uint32_t b1) {
    asm volatile("mma.sync.aligned.m16n8k16.row.col.f32.bf16.bf16.f32 "
                 "{%0,%1,%2,%3}, {%4,%5,%6,%7}, {%8,%9}, {%0,%1,%2,%3};"
                 : "+f"(c0), "+f"(c1), "+f"(c2), "+f"(c3)
                 : "r"(a0), "r"(a1), "r"(a2), "r"(a3), "r"(b0), "r"(b1));
}
#define CPA16(dst, src) \
    asm volatile("cp.async.cg.shared.global [%0], [%1], 16;" :: "r"(dst), "l"(src))
#define CPA_COMMIT() asm volatile("cp.async.commit_group;" ::: "memory")
#define CPA_WAIT(N)  asm volatile("cp.async.wait_group %0;" :: "n"(N) : "memory")

__device__ __forceinline__ void f2hilo(float x, __nv_bfloat16& h, __nv_bfloat16& l) {
    h = __float2bfloat16(x);
    l = __float2bfloat16(x - __bfloat162float(h));
}

// ---------------- kernel 1: topk+bias-init | convW | conv fcw ----------------
// blocks [0,128): per-batch top-16 of r + out=fc bias
// blocks [128,704): pool_W -> g_B  (576 = 24 k-tiles x 24 h-tiles)
// blocks [704,1472): fc_w -> g_fcB (768 = 24 k-tiles x 32 n-tiles, pad n>=1000 -> 0)
__global__ void __launch_bounds__(256) prep_kernel(
        const float* __restrict__ r, const float* __restrict__ vb,
        float* __restrict__ out, const float* __restrict__ fcb,
        const float* __restrict__ W, const float* __restrict__ fcw) {
    const int bid = blockIdx.x;
    const int t = threadIdx.x;

    if (bid >= 128) {
        __shared__ float tile[32][33];
        const int tx = t & 31, rt = t >> 5;    // 32 x 8
        if (bid < 704) {
            const int b2 = bid - 128;
            const int k0 = (b2 % 24) * 32, h0 = (b2 / 24) * 32;
#pragma unroll
            for (int i = 0; i < 4; i++)
                tile[rt + i * 8][tx] = W[(size_t)(k0 + rt + i * 8) * 768 + h0 + tx];
            __syncthreads();
#pragma unroll
            for (int i = 0; i < 4; i++) {
                const int h = h0 + rt + i * 8, k = k0 + tx;
                __nv_bfloat16 hi, lo;
                f2hilo(tile[tx][rt + i * 8], hi, lo);
                g_B[(size_t)h * 2304 + k]        = hi;
                g_B[(size_t)h * 2304 + 768 + k]  = hi;
                g_B[(size_t)h * 2304 + 1536 + k] = lo;
            }
        } else {
            const int b3 = bid - 704;
            const int k0 = (b3 % 24) * 32, n0 = (b3 / 24) * 32;
#pragma unroll
            for (int i = 0; i < 4; i++)
                tile[rt + i * 8][tx] = (n0 + tx < 1000)
                    ? fcw[(size_t)(k0 + rt + i * 8) * 1000 + n0 + tx] : 0.f;
            __syncthreads();
#pragma unroll
            for (int i = 0; i < 4; i++) {
                const int n = n0 + rt + i * 8, k = k0 + tx;
                __nv_bfloat16 hi, lo;
                f2hilo(tile[tx][rt + i * 8], hi, lo);
                g_fcB[(size_t)n * 2304 + k]        = hi;
                g_fcB[(size_t)n * 2304 + 768 + k]  = hi;
                g_fcB[(size_t)n * 2304 + 1536 + k] = lo;
            }
        }
        return;
    }

    // ---- topk + bias init ----
    const int b = bid;
    for (int n = t; n < 1000; n += 256) out[b * 1000 + n] = fcb[n];

    const int w = t >> 5, lane = t & 31;
    const float vbv = vb[0];
    float rv[16];
    const float* rp = r + b * 4096 + w * 512 + lane;
#pragma unroll
    for (int j = 0; j < 16; j++) rv[j] = rp[j * 32];

    __shared__ float cv[128];
    __shared__ int   ci[128];

    for (int it = 0; it < 16; it++) {
        float bv = rv[0]; int bs = 0;
#pragma unroll
        for (int j = 1; j < 16; j++)
            if (rv[j] > bv) { bv = rv[j]; bs = j; }
        int pay = (lane << 4) | bs;
#pragma unroll
        for (int off = 16; off; off >>= 1) {
            float ov = __shfl_xor_sync(0xffffffffu, bv, off);
            int   op = __shfl_xor_sync(0xffffffffu, pay, off);
            if (ov > bv || (ov == bv && op < pay)) { bv = ov; pay = op; }
        }
        if (lane == (pay >> 4)) {
            const int sl = pay & 15;
#pragma unroll
            for (int j = 0; j < 16; j++)
                if (sl == j) rv[j] = NEG_INF;
        }
        if (lane == 0) {
            cv[w * 16 + it] = bv;
            ci[w * 16 + it] = w * 512 + (pay >> 4) + (pay & 15) * 32;
        }
    }
    __syncthreads();

    if (w == 0) {
        float v4[4]; int i4[4];
#pragma unroll
        for (int j = 0; j < 4; j++) { v4[j] = cv[lane * 4 + j]; i4[j] = ci[lane * 4 + j]; }
        for (int it = 0; it < 16; it++) {
            float bv = v4[0]; int bs = 0;
#pragma unroll
            for (int j = 1; j < 4; j++)
                if (v4[j] > bv) { bv = v4[j]; bs = j; }
            int pay = (lane << 2) | bs;
#pragma unroll
            for (int off = 16; off; off >>= 1) {
                float ov = __shfl_xor_sync(0xffffffffu, bv, off);
                int   op = __shfl_xor_sync(0xffffffffu, pay, off);
                if (ov > bv || (ov == bv && op < pay)) { bv = ov; pay = op; }
            }
            const int slot = pay & 3, src = pay >> 2;
            if (lane == src) {
                if (slot == 0) v4[0] = NEG_INF;
                else if (slot == 1) v4[1] = NEG_INF;
                else if (slot == 2) v4[2] = NEG_INF;
                else v4[3] = NEG_INF;
            }
            const int myi = (slot == 0) ? i4[0] : (slot == 1) ? i4[1]
                          : (slot == 2) ? i4[2] : i4[3];
            const int idx = __shfl_sync(0xffffffffu, myi, src);
            if (lane == 0) {
                g_rowbase[b * 16 + it] = ((long long)b * 4096 + idx) * 768;
                g_score[b * 16 + it] = vbv;
            }
        }
    }
}

// ---------------- kernel 2: gathered x rows -> g_A = [Ah | Al | Ah] ----------------
__global__ void convX_kernel(const float* __restrict__ x) {
    const int b = blockIdx.x;     // 0..2047
    const int t = threadIdx.x;    // 192
    const float4 xv = *(const float4*)(x + g_rowbase[b] + t * 4);
    __nv_bfloat16 h0, h1, h2, h3, l0, l1, l2, l3;
    f2hilo(xv.x, h0, l0); f2hilo(xv.y, h1, l1);
    f2hilo(xv.z, h2, l2); f2hilo(xv.w, h3, l3);
    __nv_bfloat162 hh0, hh1, ll0, ll1;
    hh0.x = h0; hh0.y = h1; hh1.x = h2; hh1.y = h3;
    ll0.x = l0; ll0.y = l1; ll1.x = l2; ll1.y = l3;
    __nv_bfloat162* p0 = (__nv_bfloat162*)&g_A[(size_t)b * 2304 + t * 4];
    __nv_bfloat162* p1 = (__nv_bfloat162*)&g_A[(size_t)b * 2304 + 768 + t * 4];
    __nv_bfloat162* p2 = (__nv_bfloat162*)&g_A[(size_t)b * 2304 + 1536 + t * 4];
    p0[0] = hh0; p0[1] = hh1;
    p1[0] = ll0; p1[1] = ll1;
    p2[0] = hh0; p2[1] = hh1;
}

// ---------------- kernel 3: mma GEMM1 + tanh + v-dot epilogue ----------------
// Tile 64x64, BK=32, 128 thr / 4 warps (2m x 2n, warp tile 32x32),
// 3-stage cp.async pipeline. grid (12, 32) = 384 blocks.
static constexpr int G1_NS = 72;   // 2304/32

__global__ void __launch_bounds__(128) gemm1_mma(const float* __restrict__ Wb,
                                                 const float* __restrict__ v) {
    __shared__ __nv_bfloat16 As[3][64 * 40];
    __shared__ __nv_bfloat16 Bs[3][64 * 40];
    __shared__ float sWb[64], sv[64];

    const int t = threadIdx.x, lane = t & 31, w = t >> 5;
    const int wm = w & 1, wn = w >> 1;
    const int n0 = blockIdx.x * 64, m0 = blockIdx.y * 64;
    if (t < 64) { sWb[t] = Wb[n0 + t]; sv[t] = v[n0 + t]; }

    const int r0 = t >> 2, kc0 = (t & 3) * 8;     // rows r0, r0+32
    const uint32_t sA = smem_u32(As), sB = smem_u32(Bs);
    const uint32_t dOff = (uint32_t)(r0 * 40 + kc0) * 2u;

#define G1_ISSUE(S, BUF)                                                        \
    {                                                                           \
        const uint32_t dA = sA + (BUF) * 5120u + dOff;                          \
        const uint32_t dB = sB + (BUF) * 5120u + dOff;                          \
        CPA16(dA,         &g_A[(size_t)(m0 + r0) * 2304 + (S) * 32 + kc0]);     \
        CPA16(dA + 2560u, &g_A[(size_t)(m0 + r0 + 32) * 2304 + (S) * 32 + kc0]);\
        CPA16(dB,         &g_B[(size_t)(n0 + r0) * 2304 + (S) * 32 + kc0]);     \
        CPA16(dB + 2560u, &g_B[(size_t)(n0 + r0 + 32) * 2304 + (S) * 32 + kc0]);\
    }

    const uint32_t aoff = (uint32_t)((wm * 32 + (lane & 15)) * 40 + (lane >> 4) * 8) * 2u;
    const uint32_t boff = (uint32_t)((wn * 32 + (lane & 7) + (lane >> 4) * 8) * 40 +
                                     ((lane >> 3) & 1) * 8) * 2u;

    float acc[2][4][4];
#pragma unroll
    for (int i = 0; i < 2; i++)
#pragma unroll
        for (int j = 0; j < 4; j++)
#pragma unroll
            for (int c = 0; c < 4; c++) acc[i][j][c] = 0.f;

    G1_ISSUE(0, 0); CPA_COMMIT();
    G1_ISSUE(1, 1); CPA_COMMIT();

    for (int s = 0; s < G1_NS; s++) {
        const int buf = s % 3;
        CPA_WAIT(1);
        __syncthreads();
        if (s + 2 < G1_NS) { const int nb = (s + 2) % 3; G1_ISSUE(s + 2, nb); }
        CPA_COMMIT();

        const uint32_t ab = sA + (uint32_t)buf * 5120u;
        const uint32_t bb = sB + (uint32_t)buf * 5120u;
#pragma unroll
        for (int ks = 0; ks < 2; ks++) {
            uint32_t a[2][4], b2[4][2];
#pragma unroll
            for (int i = 0; i < 2; i++)
                ldsm_x4(a[i][0], a[i][1], a[i][2], a[i][3],
                        ab + aoff + (uint32_t)(i * 16 * 40 + ks * 16) * 2u);
#pragma unroll
            for (int jp = 0; jp < 2; jp++)
                ldsm_x4(b2[jp * 2][0], b2[jp * 2][1], b2[jp * 2 + 1][0], b2[jp * 2 + 1][1],
                        bb + boff + (uint32_t)(jp * 16 * 40 + ks * 16) * 2u);
#pragma unroll
            for (int i = 0; i < 2; i++)
#pragma unroll
                for (int j = 0; j < 4; j++)
                    mma16816(acc[i][j][0], acc[i][j][1], acc[i][j][2], acc[i][j][3],
                             a[i][0], a[i][1], a[i][2], a[i][3], b2[j][0], b2[j][1]);
        }
        __syncthreads();
    }

    // epilogue: row = wm*32+i*16+lane/4 (+8 for c>=2), col = wn*32+(lane&3)*2+j*8+(c&1)
    const int cb = wn * 32 + (lane & 3) * 2;
#pragma unroll
    for (int i = 0; i < 2; i++) {
        float pA = 0.f, pB = 0.f;
#pragma unroll
        for (int j = 0; j < 4; j++) {
            const int n = cb + j * 8;
            pA += tanhf(acc[i][j][0] + sWb[n]) * sv[n] +
                  tanhf(acc[i][j][1] + sWb[n + 1]) * sv[n + 1];
            pB += tanhf(acc[i][j][2] + sWb[n]) * sv[n] +
                  tanhf(acc[i][j][3] + sWb[n + 1]) * sv[n + 1];
        }
        pA += __shfl_xor_sync(0xffffffffu, pA, 1);
        pA += __shfl_xor_sync(0xffffffffu, pA, 2);
        pB += __shfl_xor_sync(0xffffffffu, pB, 1);
        pB += __shfl_xor_sync(0xffffffffu, pB, 2);
        if ((lane & 3) == 0) {
            const int m = m0 + wm * 32 + i * 16 + (lane >> 2);
            atomicAdd(&g_score[m], pA);
            atomicAdd(&g_score[m + 8], pB);
        }
    }
}

// ---------------- kernel 4: softmax + z, emit z as [zh | zl | zh] ----------------
// 128 blocks x 768 threads; alpha computed ONCE per block (lane 0 -> shared),
// one float column per thread, fully coalesced.
__global__ void __launch_bounds__(768) softz_kernel(const float* __restrict__ x) {
    __shared__ float s_al[16];
    __shared__ long long s_rb[16];

    const int b = blockIdx.x;
    const int t = threadIdx.x;

    if (t < 16) s_rb[t] = g_rowbase[b * 16 + t];
    if (t == 0) {
        float sc[16];
#pragma unroll
        for (int k = 0; k < 16; k++) sc[k] = g_score[b * 16 + k];
        float mx = sc[0];
#pragma unroll
        for (int k = 1; k < 16; k++) mx = fmaxf(mx, sc[k]);
        float sum = 0.f;
#pragma unroll
        for (int k = 0; k < 16; k++) { sc[k] = expf(sc[k] - mx); sum += sc[k]; }
        const float inv = 1.0f / sum;
#pragma unroll
        for (int k = 0; k < 16; k++) s_al[k] = sc[k] * inv;
    }
    __syncthreads();

    float z = 0.f;
#pragma unroll
    for (int k = 0; k < 16; k++) z += s_al[k] * x[s_rb[k] + t];

    __nv_bfloat16 h, l;
    f2hilo(z, h, l);
    g_zA[(size_t)b * 2304 + t]        = h;
    g_zA[(size_t)b * 2304 + 768 + t]  = l;
    g_zA[(size_t)b * 2304 + 1536 + t] = h;
}

// ---------------- kernel 5: fc via mma, split-K'x6, atomicAdd ----------------
// Tile 64x64, BK=32, 128 thr, grid (16, 2, 6); out pre-initialized with bias.
static constexpr int FC_NS = 12;   // 384/32

__global__ void __launch_bounds__(128) fc_mma(float* __restrict__ out) {
    __shared__ __nv_bfloat16 As[3][64 * 40];
    __shared__ __nv_bfloat16 Bs[3][64 * 40];

    const int t = threadIdx.x, lane = t & 31, w = t >> 5;
    const int wm = w & 1, wn = w >> 1;
    const int n0 = blockIdx.x * 64, m0 = blockIdx.y * 64;
    const int kb = blockIdx.z * 384;

    const int r0 = t >> 2, kc0 = (t & 3) * 8;
    const uint32_t sA = smem_u32(As), sB = smem_u32(Bs);
    const uint32_t dOff = (uint32_t)(r0 * 40 + kc0) * 2u;

#define FC_ISSUE(S, BUF)                                                             \
    {                                                                                \
        const uint32_t dA = sA + (BUF) * 5120u + dOff;                               \
        const uint32_t dB = sB + (BUF) * 5120u + dOff;                               \
        CPA16(dA,         &g_zA[(size_t)(m0 + r0) * 2304 + kb + (S) * 32 + kc0]);    \
        CPA16(dA + 2560u, &g_zA[(size_t)(m0 + r0 + 32) * 2304 + kb + (S) * 32 + kc0]);\
        CPA16(dB,         &g_fcB[(size_t)(n0 + r0) * 2304 + kb + (S) * 32 + kc0]);   \
        CPA16(dB + 2560u, &g_fcB[(size_t)(n0 + r0 + 32) * 2304 + kb + (S) * 32 + kc0]);\
    }

    const uint32_t aoff = (uint32_t)((wm * 32 + (lane & 15)) * 40 + (lane >> 4) * 8) * 2u;
    const uint32_t boff = (uint32_t)((wn * 32 + (lane & 7) + (lane >> 4) * 8) * 40 +
                                     ((lane >> 3) & 1) * 8) * 2u;

    float acc[2][4][4];
#pragma unroll
    for (int i = 0; i < 2; i++)
#pragma unroll
        for (int j = 0; j < 4; j++)
#pragma unroll
            for (int c = 0; c < 4; c++) acc[i][j][c] = 0.f;

    FC_ISSUE(0, 0); CPA_COMMIT();
    FC_ISSUE(1, 1); CPA_COMMIT();

    for (int s = 0; s < FC_NS; s++) {
        const int buf = s % 3;
        CPA_WAIT(1);
        __syncthreads();
        if (s + 2 < FC_NS) { const int nb = (s + 2) % 3; FC_ISSUE(s + 2, nb); }
        CPA_COMMIT();

        const uint32_t ab = sA + (uint32_t)buf * 5120u;
        const uint32_t bb = sB + (uint32_t)buf * 5120u;
#pragma unroll
        for (int ks = 0; ks < 2; ks++) {
            uint32_t a[2][4], b2[4][2];
#pragma unroll
            for (int i = 0; i < 2; i++)
                ldsm_x4(a[i][0], a[i][1], a[i][2], a[i][3],
                        ab + aoff + (uint32_t)(i * 16 * 40 + ks * 16) * 2u);
#pragma unroll
            for (int jp = 0; jp < 2; jp++)
                ldsm_x4(b2[jp * 2][0], b2[jp * 2][1], b2[jp * 2 + 1][0], b2[jp * 2 + 1][1],
                        bb + boff + (uint32_t)(jp * 16 * 40 + ks * 16) * 2u);
#pragma unroll
            for (int i = 0; i < 2; i++)
#pragma unroll
                for (int j = 0; j < 4; j++)
                    mma16816(acc[i][j][0], acc[i][j][1], acc[i][j][2], acc[i][j][3],
                             a[i][0], a[i][1], a[i][2], a[i][3], b2[j][0], b2[j][1]);
        }
        __syncthreads();
    }

#pragma unroll
    for (int i = 0; i < 2; i++) {
        const int m = m0 + wm * 32 + i * 16 + (lane >> 2);
#pragma unroll
        for (int j = 0; j < 4; j++) {
            const int n = n0 + wn * 32 + (lane & 3) * 2 + j * 8;
            if (n < 1000) {
                atomicAdd(&out[m * 1000 + n], acc[i][j][0]);
                atomicAdd(&out[(m + 8) * 1000 + n], acc[i][j][2]);
            }
            if (n + 1 < 1000) {
                atomicAdd(&out[m * 1000 + n + 1], acc[i][j][1]);
                atomicAdd(&out[(m + 8) * 1000 + n + 1], acc[i][j][3]);
            }
        }
    }
}

// ---------------- launch ----------------
extern "C" void kernel_launch(void* const* d_in, const int* in_sizes, int n_in,
                              void* d_out, int out_size) {
    const float* x    = (const float*)d_in[0];   // [128,4096,768]
    const float* r    = (const float*)d_in[1];   // [128,4096]
    const float* pWw  = (const float*)d_in[2];   // [768,768]
    const float* pWb  = (const float*)d_in[3];   // [768]
    const float* pVw  = (const float*)d_in[4];   // [768,1]
    const float* pVb  = (const float*)d_in[5];   // [1]
    const float* fcw  = (const float*)d_in[6];   // [768,1000]
    const float* fcb  = (const float*)d_in[7];   // [1000]
    float* out = (float*)d_out;                  // [128,1000]

    prep_kernel<<<1472, 256>>>(r, pVb, out, fcb, pWw, fcw);
    convX_kernel<<<2048, 192>>>(x);
    gemm1_mma<<<dim3(12, 32), 128>>>(pWb, pVw);
    softz_kernel<<<128, 768>>>(x);
    fc_mma<<<dim3(16, 2, 6), 128>>>(out);
}